// round 14
// baseline (speedup 1.0000x reference)
#include <cuda_runtime.h>
#include <cuda_bf16.h>
#include <cstdint>

#define Bb 32
#define Ss 2048
#define Dd 1024
#define NSPLIT 8
#define SCHUNK (Ss / NSPLIT)      // 256 (pool)
#define PREPZ 16
#define PCHUNK (Ss / PREPZ)       // 128 (prep)

// ---------------- scratch (device globals; no allocation allowed) ----------------
__device__ alignas(16) __nv_bfloat16 g_Wt[(size_t)Dd * Dd];         // Wt[e][d] = Wl[d][e]
__device__ alignas(16) float g_Wlt[(size_t)Dd * Dd];                // fp32 transpose of Wl
__device__ alignas(16) float g_gsum_part[PREPZ * Bb * Dd];
__device__ float g_gppart[8 * Bb * Dd];
__device__ float g_gp[Bb * Dd];       // RAW (unnormalized) gp
__device__ float g_rsq[Bb];
__device__ float g_vpart[16 * Bb * Dd];
__device__ alignas(16) float g_v[Bb * Dd];   // v = (Wl @ gp) * rsq (fp32 exact)
__device__ float g_nrm[Bb * Ss];             // ||x @ Wl||^2 per token
__device__ alignas(16) float g_out_part[NSPLIT * Bb * Dd];
__device__ int g_flag[Bb * 16];              // per norm-tile completion flags

// ---------------- helpers ----------------------------------------------------------
__device__ __forceinline__ uint32_t smem_u32(const void* p) {
    return (uint32_t)__cvta_generic_to_shared(p);
}
__device__ __forceinline__ void cpa16(uint32_t dst, const void* src) {
    asm volatile("cp.async.cg.shared.global [%0], [%1], 16;\n" :: "r"(dst), "l"(src));
}
__device__ __forceinline__ void ldsm4(uint32_t& r0, uint32_t& r1, uint32_t& r2, uint32_t& r3,
                                      uint32_t addr) {
    asm volatile("ldmatrix.sync.aligned.m8n8.x4.shared.b16 {%0,%1,%2,%3}, [%4];"
                 : "=r"(r0), "=r"(r1), "=r"(r2), "=r"(r3) : "r"(addr));
}
__device__ __forceinline__ void mma_bf16(float c[4], uint32_t a0, uint32_t a1, uint32_t a2,
                                         uint32_t a3, uint32_t b0, uint32_t b1) {
    asm volatile(
        "mma.sync.aligned.m16n8k16.row.col.f32.bf16.bf16.f32 "
        "{%0,%1,%2,%3},{%4,%5,%6,%7},{%8,%9},{%0,%1,%2,%3};\n"
        : "+f"(c[0]), "+f"(c[1]), "+f"(c[2]), "+f"(c[3])
        : "r"(a0), "r"(a1), "r"(a2), "r"(a3), "r"(b0), "r"(b1));
}
__device__ __forceinline__ uint32_t pack2(float a, float b) {
    __nv_bfloat162 t = __floats2bfloat162_rn(a, b);
    return *reinterpret_cast<uint32_t*>(&t);
}
__device__ __forceinline__ void st_rel(int* p, int v) {
    asm volatile("st.global.release.gpu.b32 [%0], %1;" :: "l"(p), "r"(v) : "memory");
}
__device__ __forceinline__ int ld_acq(const int* p) {
    int v;
    asm volatile("ld.global.acquire.gpu.b32 %0, [%1];" : "=r"(v) : "l"(p) : "memory");
    return v;
}

// ---------------- K0: transpose Wl -> bf16 g_Wt + fp32 g_Wlt (+ flag reset) -------
__global__ void k_transpose(const float* __restrict__ Wl) {
    __shared__ float tile[32][33];
    int x = blockIdx.x * 32 + threadIdx.x;
    int y = blockIdx.y * 32 + threadIdx.y;
    if (blockIdx.x == 0 && blockIdx.y == 0) {
        int tid = threadIdx.y * 32 + threadIdx.x;
        if (tid < Bb * 16) g_flag[tid] = 0;     // reset tile flags (ordered before k_norm)
    }
    tile[threadIdx.y][threadIdx.x] = Wl[(size_t)y * Dd + x];
    __syncthreads();
    int xo = blockIdx.y * 32 + threadIdx.x;   // d
    int yo = blockIdx.x * 32 + threadIdx.y;   // e
    float v = tile[threadIdx.x][threadIdx.y];
    g_Wt[(size_t)yo * Dd + xo]  = __float2bfloat16(v);
    g_Wlt[(size_t)yo * Dd + xo] = v;
}

// ---------------- K1: masked seq-sum partials only (no bf16 copy) ------------------
__global__ void __launch_bounds__(256) k_prep2(const float* __restrict__ X,
                                               const int* __restrict__ lengths) {
    int b = blockIdx.y, z = blockIdx.z;
    int t = threadIdx.x;
    int len = lengths[b], s0 = z * PCHUNK;
    const float4* Xb = reinterpret_cast<const float4*>(X + (size_t)b * Ss * Dd) + t;

    float4 acc = make_float4(0.f, 0.f, 0.f, 0.f);
    int send = min(len, s0 + PCHUNK);
    for (int s = s0; s < send; ++s) {
        float4 x0 = Xb[(size_t)s * 256];
        acc.x += x0.x; acc.y += x0.y; acc.z += x0.z; acc.w += x0.w;
    }
    reinterpret_cast<float4*>(g_gsum_part)[((size_t)z * Bb + b) * 256 + t] = acc;
}

// ---------------- gp chain: read Wg once, b-batched --------------------------------
__global__ void k_gp1(const float* __restrict__ Wg) {
    __shared__ float sgs[32][128];
    int tid = threadIdx.x;
    int y = blockIdx.y;                 // d2-split of 8
    for (int idx = tid; idx < 32 * 128; idx += 256) {
        int b2 = idx >> 7, d = idx & 127;
        float s = 0.f;
        #pragma unroll
        for (int z = 0; z < PREPZ; ++z)
            s += g_gsum_part[((size_t)z * Bb + b2) * Dd + y * 128 + d];
        sgs[b2][d] = s;
    }
    __syncthreads();
    int col = blockIdx.x * 256 + tid;
    float acc[32];
    #pragma unroll
    for (int b2 = 0; b2 < 32; ++b2) acc[b2] = 0.f;
    for (int d2 = 0; d2 < 128; ++d2) {
        float w = Wg[(size_t)(y * 128 + d2) * Dd + col];
        #pragma unroll
        for (int b2 = 0; b2 < 32; ++b2) acc[b2] = fmaf(sgs[b2][d2], w, acc[b2]);
    }
    #pragma unroll
    for (int b2 = 0; b2 < 32; ++b2)
        g_gppart[((size_t)y * Bb + b2) * Dd + col] = acc[b2];
}

__global__ void k_gp2() {
    int b = blockIdx.x, tid = threadIdx.x;
    int lane = tid & 31, warp = tid >> 5;
    __shared__ float red[8];
    float sq = 0.f;
    for (int c = tid; c < Dd; c += 256) {
        float s = 0.f;
        #pragma unroll
        for (int z = 0; z < 8; ++z) s += g_gppart[((size_t)z * Bb + b) * Dd + c];
        g_gp[b * Dd + c] = s;
        sq += s * s;
    }
    #pragma unroll
    for (int o = 16; o; o >>= 1) sq += __shfl_xor_sync(0xffffffffu, sq, o);
    if (lane == 0) red[warp] = sq;
    __syncthreads();
    if (tid == 0) {
        float t = 0.f;
        #pragma unroll
        for (int w = 0; w < 8; ++w) t += red[w];
        g_rsq[b] = rsqrtf(fmaxf(t, 1e-12f));
    }
}

// ---------------- v chain: v = (Wl @ gp) * rsq, read Wlt once ----------------------
__global__ void k_v1() {
    __shared__ float sgp[32][64];
    int tid = threadIdx.x;
    int y = blockIdx.y;                 // e-split of 16
    for (int idx = tid; idx < 32 * 64; idx += 256) {
        int b2 = idx >> 6, e = idx & 63;
        sgp[b2][e] = g_gp[b2 * Dd + y * 64 + e];
    }
    __syncthreads();
    int col = blockIdx.x * 256 + tid;
    float acc[32];
    #pragma unroll
    for (int b2 = 0; b2 < 32; ++b2) acc[b2] = 0.f;
    for (int e = 0; e < 64; ++e) {
        float w = g_Wlt[(size_t)(y * 64 + e) * Dd + col];
        #pragma unroll
        for (int b2 = 0; b2 < 32; ++b2) acc[b2] = fmaf(sgp[b2][e], w, acc[b2]);
    }
    #pragma unroll
    for (int b2 = 0; b2 < 32; ++b2)
        g_vpart[((size_t)y * Bb + b2) * Dd + col] = acc[b2];
}

__global__ void k_v2() {
    int i = blockIdx.x * 256 + threadIdx.x;
    int b = i >> 10;
    float s = 0.f;
    #pragma unroll
    for (int z = 0; z < 16; ++z) s += g_vpart[(size_t)z * Bb * Dd + i];
    g_v[i] = s * g_rsq[b];
}

// ---------------- K3: HMMA GEMM, in-kernel fp32->bf16 A conversion -----------------
// CTA 128 rows x N=1024 x K=1024; slab = 32 K-elems; 4-stage; 8 warps 2Mx4N.
// ONE 512-CTA wave (2 CTA/SM co-residency required; R11). Sets per-tile flag at end.
#define PITCH 80
#define STG_BYTES (128 * PITCH)                   // 10240
#define SA_OFF(st) ((uint32_t)(st) * 2u * STG_BYTES)
#define SB_OFF(st) ((uint32_t)(st) * 2u * STG_BYTES + STG_BYTES)
#define REDN_OFF 81920
#define NORM_SMEM 84096

__device__ __forceinline__ void fill_b(uint32_t sb, int g, int tid) {
    int st = g & 3, slab = g & 31, nt = g >> 5;
    const char* Bbase = (const char*)g_Wt + (size_t)(nt * 128) * 2048;
    #pragma unroll
    for (int rep = 0; rep < 2; ++rep) {
        int id = tid + rep * 256;
        int r = id >> 2, c = id & 3;
        cpa16(sb + SB_OFF(st) + (uint32_t)(r * PITCH + c * 16),
              Bbase + (size_t)r * 2048 + slab * 64 + c * 16);
    }
}

__global__ void __launch_bounds__(256, 2) k_norm(const float* __restrict__ X,
                                                 const int* __restrict__ lengths) {
    extern __shared__ __align__(128) char sm[];
    const int rows_base = blockIdx.x * 128;
    const int b = rows_base >> 11;
    const int s0loc = rows_base & (Ss - 1);
    const int len = lengths[b];
    if (s0loc >= len) return;

    const uint32_t sb = smem_u32(sm);
    float* redN = (float*)(sm + REDN_OFF);   // [4][128]

    const int tid = threadIdx.x;
    const int warp = tid >> 5, lane = tid & 31;
    const int wm = warp & 1, wn = warp >> 1;
    const int gid = lane >> 2, tig = lane & 3;
    const uint32_t lanebyte = (uint32_t)((lane & 15) * PITCH + (lane >> 4) * 16);

    // A-fill geometry (fixed per thread): item rep -> row r, 16B-bf16 chunk c
    int rA[2], cA[2], validA[2];
    const float* srcA[2];
    #pragma unroll
    for (int rep = 0; rep < 2; ++rep) {
        int id = tid + rep * 256;
        rA[rep] = id >> 2; cA[rep] = id & 3;
        validA[rep] = (s0loc + rA[rep]) < len;
        srcA[rep] = X + (size_t)(rows_base + rA[rep]) * Dd + cA[rep] * 8;
    }
    const float4 fz = make_float4(0.f, 0.f, 0.f, 0.f);

    // prologue: stages 0..2 (B async, A synchronous convert)
    #pragma unroll
    for (int g = 0; g < 3; ++g) {
        fill_b(sb, g, tid);
        asm volatile("cp.async.commit_group;");
        #pragma unroll
        for (int rep = 0; rep < 2; ++rep) {
            const float4* s4 = reinterpret_cast<const float4*>(srcA[rep] + g * 32);
            float4 v0 = validA[rep] ? s4[0] : fz;
            float4 v1 = validA[rep] ? s4[1] : fz;
            uint4 o;
            o.x = pack2(v0.x, v0.y); o.y = pack2(v0.z, v0.w);
            o.z = pack2(v1.x, v1.y); o.w = pack2(v1.z, v1.w);
            *reinterpret_cast<uint4*>(sm + SA_OFF(g) + rA[rep] * PITCH + cA[rep] * 16) = o;
        }
    }

    float acc[4][4][4];
    #pragma unroll
    for (int i = 0; i < 4; ++i)
        #pragma unroll
        for (int j = 0; j < 4; ++j)
            #pragma unroll
            for (int q = 0; q < 4; ++q) acc[i][j][q] = 0.f;
    float rsN[4][2];
    #pragma unroll
    for (int i = 0; i < 4; ++i) { rsN[i][0] = 0.f; rsN[i][1] = 0.f; }

    for (int g = 0; g < 256; ++g) {
        asm volatile("cp.async.wait_group 2;");
        __syncthreads();
        const int pend = (g + 3 < 256);
        if (pend) fill_b(sb, g + 3, tid);
        asm volatile("cp.async.commit_group;");

        // A loads for stage g+3 (issued before MMA; consumed after)
        float4 va[2][2];
        if (pend) {
            const int slab = (g + 3) & 31;
            #pragma unroll
            for (int rep = 0; rep < 2; ++rep) {
                const float4* s4 = reinterpret_cast<const float4*>(srcA[rep] + slab * 32);
                va[rep][0] = validA[rep] ? s4[0] : fz;
                va[rep][1] = validA[rep] ? s4[1] : fz;
            }
        }

        const uint32_t sa = sb + SA_OFF(g & 3);
        const uint32_t sB = sb + SB_OFF(g & 3);
        #pragma unroll
        for (int kg = 0; kg < 2; ++kg) {
            uint32_t a[4][4];
            #pragma unroll
            for (int i = 0; i < 4; ++i)
                ldsm4(a[i][0], a[i][1], a[i][2], a[i][3],
                      sa + (uint32_t)((wm * 64 + i * 16) * PITCH + kg * 32) + lanebyte);
            uint32_t bb[2][4];
            #pragma unroll
            for (int j2 = 0; j2 < 2; ++j2)
                ldsm4(bb[j2][0], bb[j2][1], bb[j2][2], bb[j2][3],
                      sB + (uint32_t)((wn * 32 + j2 * 16) * PITCH + kg * 32) + lanebyte);
            #pragma unroll
            for (int i = 0; i < 4; ++i)
                #pragma unroll
                for (int j = 0; j < 4; ++j)
                    mma_bf16(acc[i][j], a[i][0], a[i][1], a[i][2], a[i][3],
                             bb[j >> 1][j & 1], bb[j >> 1][(j & 1) + 2]);
        }

        // convert + store A stage g+3 (stage (g+3)&3 last read in iter g-1; safe)
        if (pend) {
            const int st = (g + 3) & 3;
            #pragma unroll
            for (int rep = 0; rep < 2; ++rep) {
                uint4 o;
                o.x = pack2(va[rep][0].x, va[rep][0].y);
                o.y = pack2(va[rep][0].z, va[rep][0].w);
                o.z = pack2(va[rep][1].x, va[rep][1].y);
                o.w = pack2(va[rep][1].z, va[rep][1].w);
                *reinterpret_cast<uint4*>(sm + SA_OFF(st) + rA[rep] * PITCH + cA[rep] * 16) = o;
            }
        }

        if ((g & 31) == 31) {     // end of N-tile: fold squares, reset acc
            #pragma unroll
            for (int j = 0; j < 4; ++j)
                #pragma unroll
                for (int i = 0; i < 4; ++i) {
                    rsN[i][0] += acc[i][j][0] * acc[i][j][0] + acc[i][j][1] * acc[i][j][1];
                    rsN[i][1] += acc[i][j][2] * acc[i][j][2] + acc[i][j][3] * acc[i][j][3];
                    acc[i][j][0] = acc[i][j][1] = acc[i][j][2] = acc[i][j][3] = 0.f;
                }
        }
    }

    #pragma unroll
    for (int i = 0; i < 4; ++i) {
        #pragma unroll
        for (int h = 0; h < 2; ++h) {
            float n = rsN[i][h];
            n += __shfl_xor_sync(0xffffffffu, n, 1);
            n += __shfl_xor_sync(0xffffffffu, n, 2);
            if (tig == 0) redN[wn * 128 + wm * 64 + i * 16 + gid + h * 8] = n;
        }
    }
    __syncthreads();
    if (tid < 128) {
        float n = (redN[tid] + redN[128 + tid]) + (redN[256 + tid] + redN[384 + tid]);
        g_nrm[rows_base + tid] = n;
    }
    __threadfence();          // writers' g_nrm visible gpu-wide
    __syncthreads();
    if (tid == 0) st_rel(&g_flag[blockIdx.x], 1);   // signal tile done
}

// ---------------- K4: fused attention + pooling (polls norm tile flags) ------------
__global__ void __launch_bounds__(256) k_pool(const float* __restrict__ X,
                                              const int* __restrict__ lengths) {
    __shared__ float4 sOut[8][256];
    int b = blockIdx.y, z = blockIdx.x;
    int warp = threadIdx.x >> 5, lane = threadIdx.x & 31;
    int len = lengths[b];

    // wait for the two norm tiles covering tokens [z*256, z*256+256) (live only)
    if (threadIdx.x == 0) {
        int t0 = b * 16 + 2 * z;
        if (z * 256 < len)
            while (ld_acq(&g_flag[t0]) == 0) __nanosleep(200);
        if (z * 256 + 128 < len)
            while (ld_acq(&g_flag[t0 + 1]) == 0) __nanosleep(200);
    }
    __syncthreads();

    const float4* v4 = reinterpret_cast<const float4*>(g_v + (size_t)b * Dd);
    float4 vr[8];
    #pragma unroll
    for (int i = 0; i < 8; ++i) vr[i] = v4[lane + 32 * i];

    float4 oa[8];
    #pragma unroll
    for (int i = 0; i < 8; ++i) oa[i] = make_float4(0.f, 0.f, 0.f, 0.f);

    int sw0 = z * SCHUNK + warp * 32;
    int swend = min(len, sw0 + 32);
    for (int s = sw0; s < swend; ++s) {
        const float4* x4 = reinterpret_cast<const float4*>(X + ((size_t)b * Ss + s) * Dd);
        float4 xr[8];
        float t = 0.f;
        #pragma unroll
        for (int i = 0; i < 8; ++i) {
            xr[i] = x4[lane + 32 * i];
            t += xr[i].x * vr[i].x + xr[i].y * vr[i].y +
                 xr[i].z * vr[i].z + xr[i].w * vr[i].w;
        }
        #pragma unroll
        for (int o = 16; o; o >>= 1) t += __shfl_xor_sync(0xffffffffu, t, o);
        float att = t * rsqrtf(fmaxf(g_nrm[(size_t)b * Ss + s], 1e-12f));
        #pragma unroll
        for (int i = 0; i < 8; ++i) {
            oa[i].x = fmaf(att, xr[i].x, oa[i].x);
            oa[i].y = fmaf(att, xr[i].y, oa[i].y);
            oa[i].z = fmaf(att, xr[i].z, oa[i].z);
            oa[i].w = fmaf(att, xr[i].w, oa[i].w);
        }
    }
    #pragma unroll
    for (int i = 0; i < 8; ++i) sOut[warp][lane + 32 * i] = oa[i];
    __syncthreads();

    int f = threadIdx.x;             // float4 index 0..255
    float4 r = sOut[0][f];
    #pragma unroll
    for (int w = 1; w < 8; ++w) {
        float4 q = sOut[w][f];
        r.x += q.x; r.y += q.y; r.z += q.z; r.w += q.w;
    }
    reinterpret_cast<float4*>(g_out_part)[((size_t)z * Bb + b) * 256 + f] = r;
}

// ---------------- K6: combine partials ----------------------------------------------
__global__ void k_final(float* __restrict__ out) {
    int i = blockIdx.x * 256 + threadIdx.x;
    float a = 0.f;
    #pragma unroll
    for (int z = 0; z < NSPLIT; ++z) a += g_out_part[(size_t)z * Bb * Dd + i];
    out[i] = a;
}

// ---------------- launch: pool polls norm via flags ---------------------------------
//  s0: transpose(+flag reset) ──► k_norm ─────────────────────► (wait pool) final
//  s2: prep2 ► gp1 ► gp2 ──(wait transpose)── v1 ► v2 ► pool(spins on tile flags) ─┘
extern "C" void kernel_launch(void* const* d_in, const int* in_sizes, int n_in,
                              void* d_out, int out_size) {
    const float* X       = (const float*)d_in[0];
    const int*   lengths = (const int*)d_in[1];
    const float* Wg      = (const float*)d_in[2];
    const float* Wl      = (const float*)d_in[3];
    float* out = (float*)d_out;

    static cudaStream_t s2 = nullptr;
    static cudaEvent_t ev0, evT, evP;
    static int init = 0, ok = 0;
    if (!init) {
        init = 1;
        ok = (cudaStreamCreateWithFlags(&s2, cudaStreamNonBlocking) == cudaSuccess) &&
             (cudaEventCreateWithFlags(&ev0, cudaEventDisableTiming) == cudaSuccess) &&
             (cudaEventCreateWithFlags(&evT, cudaEventDisableTiming) == cudaSuccess) &&
             (cudaEventCreateWithFlags(&evP, cudaEventDisableTiming) == cudaSuccess);
    }
    cudaFuncSetAttribute(k_norm, cudaFuncAttributeMaxDynamicSharedMemorySize, NORM_SMEM);

    if (ok) {
        cudaEventRecord(ev0, 0);
        cudaStreamWaitEvent(s2, ev0, 0);
        // s0: transpose (also resets flags), then the big GEMM
        k_transpose<<<dim3(Dd / 32, Dd / 32), dim3(32, 32)>>>(Wl);
        cudaEventRecord(evT, 0);
        k_norm<<<(Bb * Ss) / 128, 256, NORM_SMEM>>>(X, lengths);
        // s2: gsum + gp chain (overlaps norm); v1 needs g_Wlt; pool needs v (stream order)
        k_prep2<<<dim3(1, Bb, PREPZ), 256, 0, s2>>>(X, lengths);
        k_gp1<<<dim3(4, 8), 256, 0, s2>>>(Wg);
        k_gp2<<<Bb, 256, 0, s2>>>();
        cudaStreamWaitEvent(s2, evT, 0);
        k_v1<<<dim3(4, 16), 256, 0, s2>>>();
        k_v2<<<(Bb * Dd) / 256, 256, 0, s2>>>();
        k_pool<<<dim3(NSPLIT, Bb), 256, 0, s2>>>(X, lengths);   // overlaps norm tail
        cudaEventRecord(evP, s2);
        // s0: final needs pool partials
        cudaStreamWaitEvent(0, evP, 0);
        k_final<<<(Bb * Dd) / 256, 256>>>(out);
    } else {  // sequential fallback (flags are set by norm before pool reads them)
        k_transpose<<<dim3(Dd / 32, Dd / 32), dim3(32, 32)>>>(Wl);
        k_prep2<<<dim3(1, Bb, PREPZ), 256>>>(X, lengths);
        k_gp1<<<dim3(4, 8), 256>>>(Wg);
        k_gp2<<<Bb, 256>>>();
        k_v1<<<dim3(4, 16), 256>>>();
        k_v2<<<(Bb * Dd) / 256, 256>>>();
        k_norm<<<(Bb * Ss) / 128, 256, NORM_SMEM>>>(X, lengths);
        k_pool<<<dim3(NSPLIT, Bb), 256>>>(X, lengths);
        k_final<<<(Bb * Dd) / 256, 256>>>(out);
    }
}

// round 16
// speedup vs baseline: 1.0086x; 1.0086x over previous
#include <cuda_runtime.h>
#include <cuda_bf16.h>
#include <cstdint>

#define Bb 32
#define Ss 2048
#define Dd 1024
#define NSPLIT 8
#define SCHUNK (Ss / NSPLIT)      // 256 (pool)
#define PREPZ 16
#define PCHUNK (Ss / PREPZ)       // 128 (prep)

// ---------------- scratch (device globals; no allocation allowed) ----------------
__device__ alignas(16) __nv_bfloat16 g_Wt[(size_t)Dd * Dd];         // Wt[e][d] = Wl[d][e]
__device__ alignas(16) float g_Wlt[(size_t)Dd * Dd];                // fp32 transpose of Wl
__device__ alignas(16) float g_gsum_part[PREPZ * Bb * Dd];
__device__ float g_gppart[8 * Bb * Dd];
__device__ float g_gp[Bb * Dd];       // RAW (unnormalized) gp
__device__ float g_rsq[Bb];
__device__ float g_vpart[16 * Bb * Dd];
__device__ alignas(16) float g_v[Bb * Dd];   // v = (Wl @ gp) * rsq (fp32 exact)
__device__ float g_nrm[Bb * Ss];             // ||x @ Wl||^2 per token

// ---------------- helpers ----------------------------------------------------------
__device__ __forceinline__ uint32_t smem_u32(const void* p) {
    return (uint32_t)__cvta_generic_to_shared(p);
}
__device__ __forceinline__ void cpa16(uint32_t dst, const void* src) {
    asm volatile("cp.async.cg.shared.global [%0], [%1], 16;\n" :: "r"(dst), "l"(src));
}
__device__ __forceinline__ void ldsm4(uint32_t& r0, uint32_t& r1, uint32_t& r2, uint32_t& r3,
                                      uint32_t addr) {
    asm volatile("ldmatrix.sync.aligned.m8n8.x4.shared.b16 {%0,%1,%2,%3}, [%4];"
                 : "=r"(r0), "=r"(r1), "=r"(r2), "=r"(r3) : "r"(addr));
}
__device__ __forceinline__ void mma_bf16(float c[4], uint32_t a0, uint32_t a1, uint32_t a2,
                                         uint32_t a3, uint32_t b0, uint32_t b1) {
    asm volatile(
        "mma.sync.aligned.m16n8k16.row.col.f32.bf16.bf16.f32 "
        "{%0,%1,%2,%3},{%4,%5,%6,%7},{%8,%9},{%0,%1,%2,%3};\n"
        : "+f"(c[0]), "+f"(c[1]), "+f"(c[2]), "+f"(c[3])
        : "r"(a0), "r"(a1), "r"(a2), "r"(a3), "r"(b0), "r"(b1));
}
__device__ __forceinline__ uint32_t pack2(float a, float b) {
    __nv_bfloat162 t = __floats2bfloat162_rn(a, b);
    return *reinterpret_cast<uint32_t*>(&t);
}

// ---------------- K0: transpose Wl -> bf16 g_Wt + fp32 g_Wlt; zero out -------------
__global__ void k_transpose(const float* __restrict__ Wl, float* __restrict__ out) {
    __shared__ float tile[32][33];
    int x = blockIdx.x * 32 + threadIdx.x;
    int y = blockIdx.y * 32 + threadIdx.y;
    if (blockIdx.y == 0) {      // 32 blocks x 1024 threads == Bb*Dd
        int i = blockIdx.x * 1024 + threadIdx.y * 32 + threadIdx.x;
        out[i] = 0.f;
    }
    tile[threadIdx.y][threadIdx.x] = Wl[(size_t)y * Dd + x];
    __syncthreads();
    int xo = blockIdx.y * 32 + threadIdx.x;   // d
    int yo = blockIdx.x * 32 + threadIdx.y;   // e
    float v = tile[threadIdx.x][threadIdx.y];
    g_Wt[(size_t)yo * Dd + xo]  = __float2bfloat16(v);
    g_Wlt[(size_t)yo * Dd + xo] = v;
}

// ---------------- K1: masked seq-sum partials ---------------------------------------
__global__ void __launch_bounds__(256) k_prep2(const float* __restrict__ X,
                                               const int* __restrict__ lengths) {
    int b = blockIdx.y, z = blockIdx.z;
    int t = threadIdx.x;
    int len = lengths[b], s0 = z * PCHUNK;
    const float4* Xb = reinterpret_cast<const float4*>(X + (size_t)b * Ss * Dd) + t;

    float4 acc = make_float4(0.f, 0.f, 0.f, 0.f);
    int send = min(len, s0 + PCHUNK);
    for (int s = s0; s < send; ++s) {
        float4 x0 = Xb[(size_t)s * 256];
        acc.x += x0.x; acc.y += x0.y; acc.z += x0.z; acc.w += x0.w;
    }
    reinterpret_cast<float4*>(g_gsum_part)[((size_t)z * Bb + b) * 256 + t] = acc;
}

// ---------------- gp chain: read Wg once, b-batched --------------------------------
__global__ void k_gp1(const float* __restrict__ Wg) {
    __shared__ float sgs[32][128];
    int tid = threadIdx.x;
    int y = blockIdx.y;                 // d2-split of 8
    for (int idx = tid; idx < 32 * 128; idx += 256) {
        int b2 = idx >> 7, d = idx & 127;
        float s = 0.f;
        #pragma unroll
        for (int z = 0; z < PREPZ; ++z)
            s += g_gsum_part[((size_t)z * Bb + b2) * Dd + y * 128 + d];
        sgs[b2][d] = s;
    }
    __syncthreads();
    int col = blockIdx.x * 256 + tid;
    float acc[32];
    #pragma unroll
    for (int b2 = 0; b2 < 32; ++b2) acc[b2] = 0.f;
    for (int d2 = 0; d2 < 128; ++d2) {
        float w = Wg[(size_t)(y * 128 + d2) * Dd + col];
        #pragma unroll
        for (int b2 = 0; b2 < 32; ++b2) acc[b2] = fmaf(sgs[b2][d2], w, acc[b2]);
    }
    #pragma unroll
    for (int b2 = 0; b2 < 32; ++b2)
        g_gppart[((size_t)y * Bb + b2) * Dd + col] = acc[b2];
}

__global__ void k_gp2() {
    int b = blockIdx.x, tid = threadIdx.x;
    int lane = tid & 31, warp = tid >> 5;
    __shared__ float red[8];
    float sq = 0.f;
    for (int c = tid; c < Dd; c += 256) {
        float s = 0.f;
        #pragma unroll
        for (int z = 0; z < 8; ++z) s += g_gppart[((size_t)z * Bb + b) * Dd + c];
        g_gp[b * Dd + c] = s;
        sq += s * s;
    }
    #pragma unroll
    for (int o = 16; o; o >>= 1) sq += __shfl_xor_sync(0xffffffffu, sq, o);
    if (lane == 0) red[warp] = sq;
    __syncthreads();
    if (tid == 0) {
        float t = 0.f;
        #pragma unroll
        for (int w = 0; w < 8; ++w) t += red[w];
        g_rsq[b] = rsqrtf(fmaxf(t, 1e-12f));
    }
}

// ---------------- v chain: v = (Wl @ gp) * rsq -------------------------------------
__global__ void k_v1() {
    __shared__ float sgp[32][64];
    int tid = threadIdx.x;
    int y = blockIdx.y;                 // e-split of 16
    for (int idx = tid; idx < 32 * 64; idx += 256) {
        int b2 = idx >> 6, e = idx & 63;
        sgp[b2][e] = g_gp[b2 * Dd + y * 64 + e];
    }
    __syncthreads();
    int col = blockIdx.x * 256 + tid;
    float acc[32];
    #pragma unroll
    for (int b2 = 0; b2 < 32; ++b2) acc[b2] = 0.f;
    for (int e = 0; e < 64; ++e) {
        float w = g_Wlt[(size_t)(y * 64 + e) * Dd + col];
        #pragma unroll
        for (int b2 = 0; b2 < 32; ++b2) acc[b2] = fmaf(sgp[b2][e], w, acc[b2]);
    }
    #pragma unroll
    for (int b2 = 0; b2 < 32; ++b2)
        g_vpart[((size_t)y * Bb + b2) * Dd + col] = acc[b2];
}

__global__ void k_v2() {
    int i = blockIdx.x * 256 + threadIdx.x;
    int b = i >> 10;
    float s = 0.f;
    #pragma unroll
    for (int z = 0; z < 16; ++z) s += g_vpart[(size_t)z * Bb * Dd + i];
    g_v[i] = s * g_rsq[b];
}

// ---------------- K3: HMMA GEMM, in-kernel fp32->bf16 A conversion -----------------
// CTA 128 rows x N=1024 x K=1024; slab = 32 K-elems; 4-stage; 8 warps 2Mx4N.
// ONE 512-CTA wave (2 CTA/SM co-residency required; R11). NO intra-kernel waits on
// other grids (R15: RF-full norm can starve helper kernels -> deadlock).
#define PITCH 80
#define STG_BYTES (128 * PITCH)                   // 10240
#define SA_OFF(st) ((uint32_t)(st) * 2u * STG_BYTES)
#define SB_OFF(st) ((uint32_t)(st) * 2u * STG_BYTES + STG_BYTES)
#define REDN_OFF 81920
#define NORM_SMEM 84096

__device__ __forceinline__ void fill_b(uint32_t sb, int g, int tid) {
    int st = g & 3, slab = g & 31, nt = g >> 5;
    const char* Bbase = (const char*)g_Wt + (size_t)(nt * 128) * 2048;
    #pragma unroll
    for (int rep = 0; rep < 2; ++rep) {
        int id = tid + rep * 256;
        int r = id >> 2, c = id & 3;
        cpa16(sb + SB_OFF(st) + (uint32_t)(r * PITCH + c * 16),
              Bbase + (size_t)r * 2048 + slab * 64 + c * 16);
    }
}

__global__ void __launch_bounds__(256, 2) k_norm(const float* __restrict__ X,
                                                 const int* __restrict__ lengths) {
    extern __shared__ __align__(128) char sm[];
    const int rows_base = blockIdx.x * 128;
    const int b = rows_base >> 11;
    const int s0loc = rows_base & (Ss - 1);
    const int len = lengths[b];
    if (s0loc >= len) return;

    const uint32_t sb = smem_u32(sm);
    float* redN = (float*)(sm + REDN_OFF);   // [4][128]

    const int tid = threadIdx.x;
    const int warp = tid >> 5, lane = tid & 31;
    const int wm = warp & 1, wn = warp >> 1;
    const int gid = lane >> 2, tig = lane & 3;
    const uint32_t lanebyte = (uint32_t)((lane & 15) * PITCH + (lane >> 4) * 16);

    // A-fill geometry (fixed per thread): item rep -> row r, 16B-bf16 chunk c
    int rA[2], cA[2], validA[2];
    const float* srcA[2];
    #pragma unroll
    for (int rep = 0; rep < 2; ++rep) {
        int id = tid + rep * 256;
        rA[rep] = id >> 2; cA[rep] = id & 3;
        validA[rep] = (s0loc + rA[rep]) < len;
        srcA[rep] = X + (size_t)(rows_base + rA[rep]) * Dd + cA[rep] * 8;
    }
    const float4 fz = make_float4(0.f, 0.f, 0.f, 0.f);

    // prologue: stages 0..2 (B async, A synchronous convert)
    #pragma unroll
    for (int g = 0; g < 3; ++g) {
        fill_b(sb, g, tid);
        asm volatile("cp.async.commit_group;");
        #pragma unroll
        for (int rep = 0; rep < 2; ++rep) {
            const float4* s4 = reinterpret_cast<const float4*>(srcA[rep] + g * 32);
            float4 v0 = validA[rep] ? s4[0] : fz;
            float4 v1 = validA[rep] ? s4[1] : fz;
            uint4 o;
            o.x = pack2(v0.x, v0.y); o.y = pack2(v0.z, v0.w);
            o.z = pack2(v1.x, v1.y); o.w = pack2(v1.z, v1.w);
            *reinterpret_cast<uint4*>(sm + SA_OFF(g) + rA[rep] * PITCH + cA[rep] * 16) = o;
        }
    }

    float acc[4][4][4];
    #pragma unroll
    for (int i = 0; i < 4; ++i)
        #pragma unroll
        for (int j = 0; j < 4; ++j)
            #pragma unroll
            for (int q = 0; q < 4; ++q) acc[i][j][q] = 0.f;
    float rsN[4][2];
    #pragma unroll
    for (int i = 0; i < 4; ++i) { rsN[i][0] = 0.f; rsN[i][1] = 0.f; }

    for (int g = 0; g < 256; ++g) {
        asm volatile("cp.async.wait_group 2;");
        __syncthreads();
        const int pend = (g + 3 < 256);
        if (pend) fill_b(sb, g + 3, tid);
        asm volatile("cp.async.commit_group;");

        // A loads for stage g+3 (issued before MMA; consumed after)
        float4 va[2][2];
        if (pend) {
            const int slab = (g + 3) & 31;
            #pragma unroll
            for (int rep = 0; rep < 2; ++rep) {
                const float4* s4 = reinterpret_cast<const float4*>(srcA[rep] + slab * 32);
                va[rep][0] = validA[rep] ? s4[0] : fz;
                va[rep][1] = validA[rep] ? s4[1] : fz;
            }
        }

        const uint32_t sa = sb + SA_OFF(g & 3);
        const uint32_t sB = sb + SB_OFF(g & 3);
        #pragma unroll
        for (int kg = 0; kg < 2; ++kg) {
            uint32_t a[4][4];
            #pragma unroll
            for (int i = 0; i < 4; ++i)
                ldsm4(a[i][0], a[i][1], a[i][2], a[i][3],
                      sa + (uint32_t)((wm * 64 + i * 16) * PITCH + kg * 32) + lanebyte);
            uint32_t bb[2][4];
            #pragma unroll
            for (int j2 = 0; j2 < 2; ++j2)
                ldsm4(bb[j2][0], bb[j2][1], bb[j2][2], bb[j2][3],
                      sB + (uint32_t)((wn * 32 + j2 * 16) * PITCH + kg * 32) + lanebyte);
            #pragma unroll
            for (int i = 0; i < 4; ++i)
                #pragma unroll
                for (int j = 0; j < 4; ++j)
                    mma_bf16(acc[i][j], a[i][0], a[i][1], a[i][2], a[i][3],
                             bb[j >> 1][j & 1], bb[j >> 1][(j & 1) + 2]);
        }

        // convert + store A stage g+3 (stage (g+3)&3 last read in iter g-1; safe)
        if (pend) {
            const int st = (g + 3) & 3;
            #pragma unroll
            for (int rep = 0; rep < 2; ++rep) {
                uint4 o;
                o.x = pack2(va[rep][0].x, va[rep][0].y);
                o.y = pack2(va[rep][0].z, va[rep][0].w);
                o.z = pack2(va[rep][1].x, va[rep][1].y);
                o.w = pack2(va[rep][1].z, va[rep][1].w);
                *reinterpret_cast<uint4*>(sm + SA_OFF(st) + rA[rep] * PITCH + cA[rep] * 16) = o;
            }
        }

        if ((g & 31) == 31) {     // end of N-tile: fold squares, reset acc
            #pragma unroll
            for (int j = 0; j < 4; ++j)
                #pragma unroll
                for (int i = 0; i < 4; ++i) {
                    rsN[i][0] += acc[i][j][0] * acc[i][j][0] + acc[i][j][1] * acc[i][j][1];
                    rsN[i][1] += acc[i][j][2] * acc[i][j][2] + acc[i][j][3] * acc[i][j][3];
                    acc[i][j][0] = acc[i][j][1] = acc[i][j][2] = acc[i][j][3] = 0.f;
                }
        }
    }

    #pragma unroll
    for (int i = 0; i < 4; ++i) {
        #pragma unroll
        for (int h = 0; h < 2; ++h) {
            float n = rsN[i][h];
            n += __shfl_xor_sync(0xffffffffu, n, 1);
            n += __shfl_xor_sync(0xffffffffu, n, 2);
            if (tig == 0) redN[wn * 128 + wm * 64 + i * 16 + gid + h * 8] = n;
        }
    }
    __syncthreads();
    if (tid < 128) {
        float n = (redN[tid] + redN[128 + tid]) + (redN[256 + tid] + redN[384 + tid]);
        g_nrm[rows_base + tid] = n;
    }
}

// ---------------- K4: fused attention + pooling; atomicAdd into out ----------------
__global__ void __launch_bounds__(256) k_pool(const float* __restrict__ X,
                                              const int* __restrict__ lengths,
                                              float* __restrict__ out) {
    __shared__ float4 sOut[8][256];
    int b = blockIdx.y, z = blockIdx.x;
    int warp = threadIdx.x >> 5, lane = threadIdx.x & 31;
    int len = lengths[b];

    const float4* v4 = reinterpret_cast<const float4*>(g_v + (size_t)b * Dd);
    float4 vr[8];
    #pragma unroll
    for (int i = 0; i < 8; ++i) vr[i] = v4[lane + 32 * i];

    float4 oa[8];
    #pragma unroll
    for (int i = 0; i < 8; ++i) oa[i] = make_float4(0.f, 0.f, 0.f, 0.f);

    int sw0 = z * SCHUNK + warp * 32;
    int swend = min(len, sw0 + 32);
    for (int s = sw0; s < swend; ++s) {
        const float4* x4 = reinterpret_cast<const float4*>(X + ((size_t)b * Ss + s) * Dd);
        float4 xr[8];
        float t = 0.f;
        #pragma unroll
        for (int i = 0; i < 8; ++i) {
            xr[i] = x4[lane + 32 * i];
            t += xr[i].x * vr[i].x + xr[i].y * vr[i].y +
                 xr[i].z * vr[i].z + xr[i].w * vr[i].w;
        }
        #pragma unroll
        for (int o = 16; o; o >>= 1) t += __shfl_xor_sync(0xffffffffu, t, o);
        float att = t * rsqrtf(fmaxf(g_nrm[(size_t)b * Ss + s], 1e-12f));
        #pragma unroll
        for (int i = 0; i < 8; ++i) {
            oa[i].x = fmaf(att, xr[i].x, oa[i].x);
            oa[i].y = fmaf(att, xr[i].y, oa[i].y);
            oa[i].z = fmaf(att, xr[i].z, oa[i].z);
            oa[i].w = fmaf(att, xr[i].w, oa[i].w);
        }
    }
    #pragma unroll
    for (int i = 0; i < 8; ++i) sOut[warp][lane + 32 * i] = oa[i];
    __syncthreads();

    int f = threadIdx.x;             // float4 index 0..255
    float4 r = sOut[0][f];
    #pragma unroll
    for (int w = 1; w < 8; ++w) {
        float4 q = sOut[w][f];
        r.x += q.x; r.y += q.y; r.z += q.z; r.w += q.w;
    }
    float* dst = out + (size_t)b * Dd + f * 4;
    atomicAdd(dst + 0, r.x);
    atomicAdd(dst + 1, r.y);
    atomicAdd(dst + 2, r.z);
    atomicAdd(dst + 3, r.w);
}

// ---------------- launch: R13 fork-join DAG, final folded into pool -----------------
//  s0: transpose(+zero out) ──► k_norm ─────────────► (wait v) pool(atomicAdd out)
//  s2: prep2 ► gp1 ► gp2 ──(wait transpose)── v1 ► v2 ─┘
extern "C" void kernel_launch(void* const* d_in, const int* in_sizes, int n_in,
                              void* d_out, int out_size) {
    const float* X       = (const float*)d_in[0];
    const int*   lengths = (const int*)d_in[1];
    const float* Wg      = (const float*)d_in[2];
    const float* Wl      = (const float*)d_in[3];
    float* out = (float*)d_out;

    static cudaStream_t s2 = nullptr;
    static cudaEvent_t ev0, evT, evV;
    static int init = 0, ok = 0;
    if (!init) {
        init = 1;
        ok = (cudaStreamCreateWithFlags(&s2, cudaStreamNonBlocking) == cudaSuccess) &&
             (cudaEventCreateWithFlags(&ev0, cudaEventDisableTiming) == cudaSuccess) &&
             (cudaEventCreateWithFlags(&evT, cudaEventDisableTiming) == cudaSuccess) &&
             (cudaEventCreateWithFlags(&evV, cudaEventDisableTiming) == cudaSuccess);
    }
    cudaFuncSetAttribute(k_norm, cudaFuncAttributeMaxDynamicSharedMemorySize, NORM_SMEM);

    if (ok) {
        cudaEventRecord(ev0, 0);
        cudaStreamWaitEvent(s2, ev0, 0);
        // s0: transpose (also zeroes out), then the big GEMM
        k_transpose<<<dim3(Dd / 32, Dd / 32), dim3(32, 32)>>>(Wl, out);
        cudaEventRecord(evT, 0);
        k_norm<<<(Bb * Ss) / 128, 256, NORM_SMEM>>>(X, lengths);
        // s2: gsum + gp chain, fully overlapped with k_norm
        k_prep2<<<dim3(1, Bb, PREPZ), 256, 0, s2>>>(X, lengths);
        k_gp1<<<dim3(4, 8), 256, 0, s2>>>(Wg);
        k_gp2<<<Bb, 256, 0, s2>>>();
        cudaStreamWaitEvent(s2, evT, 0);      // v1 needs g_Wlt from transpose
        k_v1<<<dim3(4, 16), 256, 0, s2>>>();
        k_v2<<<(Bb * Dd) / 256, 256, 0, s2>>>();
        cudaEventRecord(evV, s2);
        // s0: pool needs g_nrm (stream order) + g_v (event); writes out directly
        cudaStreamWaitEvent(0, evV, 0);
        k_pool<<<dim3(NSPLIT, Bb), 256>>>(X, lengths, out);
    } else {  // sequential fallback
        k_transpose<<<dim3(Dd / 32, Dd / 32), dim3(32, 32)>>>(Wl, out);
        k_prep2<<<dim3(1, Bb, PREPZ), 256>>>(X, lengths);
        k_gp1<<<dim3(4, 8), 256>>>(Wg);
        k_gp2<<<Bb, 256>>>();
        k_v1<<<dim3(4, 16), 256>>>();
        k_v2<<<(Bb * Dd) / 256, 256>>>();
        k_norm<<<(Bb * Ss) / 128, 256, NORM_SMEM>>>(X, lengths);
        k_pool<<<dim3(NSPLIT, Bb), 256>>>(X, lengths, out);
    }
}